// round 15
// baseline (speedup 1.0000x reference)
#include <cuda_runtime.h>
#include <cuda_bf16.h>
#include <math_constants.h>
#include <cstdint>

#define NN 50000
#define EE 800000
#define DIN 18
#define HH 128
#define NEG_SLOPE 0.2f
#define BN_EPS 1e-5f

// ---------------- scratch (no allocation allowed) ----------------
__device__ int   g_deg[NN];
__device__ int   g_fill[NN];
__device__ int   g_rowptr[NN + 1];
__device__ int   g_cols[EE];
__device__ float g_nmean[NN * DIN];
__device__ __nv_bfloat16 g_hb[NN * HH];        // bf16 node features h
__device__ __nv_bfloat16 g_hvalb[NN * HH];     // bf16 attention values
__device__ float g_ssrc[2][NN * 4];            // ping-pong score buffers
__device__ float g_sdst[2][NN * 4];
__device__ __nv_bfloat16 g_wtb[4][HH * HH];    // bf16 weights, [N][K] (col-major B)

__device__ __forceinline__ float leaky_f(float v) { return v >= 0.f ? v : NEG_SLOPE * v; }

// ---------------- CSR build ----------------
__global__ void k_zero() {
    int i = blockIdx.x * blockDim.x + threadIdx.x;
    if (i < NN) { g_deg[i] = 0; g_fill[i] = 0; }
}

__global__ void k_count(const int* __restrict__ ei) {
    int e = blockIdx.x * blockDim.x + threadIdx.x;
    if (e < EE) atomicAdd(&g_deg[ei[e]], 1);
}

__global__ void k_scan() {
    __shared__ int wsum[32];
    __shared__ int carry;
    int tid = threadIdx.x;
    int lane = tid & 31, wid = tid >> 5;
    if (tid == 0) { carry = 0; g_rowptr[0] = 0; }
    __syncthreads();
    for (int base = 0; base < NN; base += 1024) {
        int idx = base + tid;
        int v = (idx < NN) ? g_deg[idx] : 0;
        int x = v;
        #pragma unroll
        for (int o = 1; o < 32; o <<= 1) {
            int y = __shfl_up_sync(0xffffffffu, x, o);
            if (lane >= o) x += y;
        }
        if (lane == 31) wsum[wid] = x;
        __syncthreads();
        if (wid == 0) {
            int s = wsum[lane];
            #pragma unroll
            for (int o = 1; o < 32; o <<= 1) {
                int y = __shfl_up_sync(0xffffffffu, s, o);
                if (lane >= o) s += y;
            }
            wsum[lane] = s;
        }
        __syncthreads();
        int incl = x + (wid ? wsum[wid - 1] : 0) + carry;
        if (idx < NN) g_rowptr[idx + 1] = incl;
        __syncthreads();
        if (tid == 1023) carry = incl;
        __syncthreads();
    }
}

__global__ void k_scatter(const int* __restrict__ ei) {
    int e = blockIdx.x * blockDim.x + threadIdx.x;
    if (e < EE) {
        int r = ei[e];
        int pos = g_rowptr[r] + atomicAdd(&g_fill[r], 1);
        g_cols[pos] = ei[EE + e];
    }
}

// ---------------- neighbor mean (warp per node) ----------------
__global__ void k_nmean(const float* __restrict__ x) {
    int w = (blockIdx.x * blockDim.x + threadIdx.x) >> 5;
    int lane = threadIdx.x & 31;
    if (w >= NN) return;
    int s0 = g_rowptr[w], e0 = g_rowptr[w + 1];
    float acc = 0.f;
    for (int j = s0; j < e0; j++) {
        int c = __ldg(&g_cols[j]);
        if (lane < DIN) acc += __ldg(&x[c * DIN + lane]);
    }
    float inv = 1.f / ((float)(e0 - s0) + 1e-8f);
    if (lane < DIN) g_nmean[w * DIN + lane] = acc * inv;
}

// ---------------- input transform (writes bf16 h) ----------------
__global__ void k_input(const float* __restrict__ x, const float* __restrict__ Win,
                        const float* __restrict__ bin, const float* __restrict__ Wagg,
                        const float* __restrict__ bagg) {
    __shared__ float xs[32][DIN];
    __shared__ float ns[32][DIN];
    int f = threadIdx.x;   // 128
    int n0 = blockIdx.x * 32;
    for (int t = f; t < 32 * DIN; t += 128) {
        int m = t / DIN, k = t % DIN;
        int gn = n0 + m;
        xs[m][k] = (gn < NN) ? x[gn * DIN + k] : 0.f;
        ns[m][k] = (gn < NN) ? g_nmean[gn * DIN + k] : 0.f;
    }
    float wi[DIN], wa[DIN];
    #pragma unroll
    for (int k = 0; k < DIN; k++) { wi[k] = Win[k * HH + f]; wa[k] = Wagg[k * HH + f]; }
    float bias = bin[f] + bagg[f];
    __syncthreads();
    for (int m = 0; m < 32; m++) {
        int gn = n0 + m;
        if (gn >= NN) break;
        float acc = bias;
        #pragma unroll
        for (int k = 0; k < DIN; k++) acc += xs[m][k] * wi[k] + ns[m][k] * wa[k];
        g_hb[(size_t)gn * HH + f] = __float2bfloat16(acc);
    }
}

// ---------------- weight pre-pass: bf16, transposed to [N][K] ----------------
__global__ void k_wt(const float* __restrict__ shWv, const float* __restrict__ mhWv,
                     const float* __restrict__ Wo1) {
    int t = blockIdx.x * blockDim.x + threadIdx.x;     // 4 * 16384
    int buf = t >> 14;
    int r = t & 16383;
    int n = r >> 7, k = r & 127;
    float v;
    if (buf == 1) {
        int h = n >> 5, e = n & 31;
        v = mhWv[(h * HH + k) * 32 + e];
    } else if (buf == 0) {
        v = shWv[k * HH + n];
    } else if (buf == 2) {
        v = shWv[HH * HH + k * HH + n];
    } else {
        v = Wo1[k * HH + n];
    }
    g_wtb[buf][n * HH + k] = __float2bfloat16(v);
}

// ---------------- mma.sync GEMM: g_hvalb = bf16(h @ W + bias [leaky]) ----------------
#define GM_STRIDE 136
#define GM_SM_B 34816
#define GM_SM_TOTAL 69632

#define MMA16816(c, a, b) \
    asm volatile("mma.sync.aligned.m16n8k16.row.col.f32.bf16.bf16.f32 " \
        "{%0,%1,%2,%3}, {%4,%5,%6,%7}, {%8,%9}, {%0,%1,%2,%3};" \
        : "+f"((c)[0]), "+f"((c)[1]), "+f"((c)[2]), "+f"((c)[3]) \
        : "r"((a)[0]), "r"((a)[1]), "r"((a)[2]), "r"((a)[3]), \
          "r"((b)[0]), "r"((b)[1]))

__global__ void __launch_bounds__(256) k_gemm_mma(int widx, const float* __restrict__ bias,
                                                  int act) {
    extern __shared__ __align__(16) char smem[];
    __nv_bfloat16* As = (__nv_bfloat16*)smem;
    __nv_bfloat16* Bs = (__nv_bfloat16*)(smem + GM_SM_B);
    int tid = threadIdx.x, lane = tid & 31, wid = tid >> 5;
    int row0 = blockIdx.x * 128;

    // ---- copy A rows (bf16, direct uint4) ----
    {
        int r = tid >> 1, halfq = tid & 1;
        int gr = row0 + r;
        const uint4* src = (const uint4*)&g_hb[(size_t)gr * HH + halfq * 64];
        uint4* dst = (uint4*)&As[r * GM_STRIDE + halfq * 64];
        if (gr < NN) {
            #pragma unroll
            for (int q = 0; q < 8; q++) dst[q] = __ldg(&src[q]);
        } else {
            uint4 z = make_uint4(0, 0, 0, 0);
            #pragma unroll
            for (int q = 0; q < 8; q++) dst[q] = z;
        }
    }
    // ---- copy Wt bf16 gmem -> smem ----
    {
        const uint4* src = (const uint4*)g_wtb[widx];
        #pragma unroll
        for (int i = 0; i < 8; i++) {
            int idx = tid + i * 256;
            int n = idx >> 4, j = idx & 15;
            *(uint4*)&Bs[n * GM_STRIDE + j * 8] = src[n * 16 + j];
        }
    }
    __syncthreads();

    int mw = wid & 1, nw = wid >> 1;
    int m0 = mw * 64, n0 = nw * 32;
    int gid = lane >> 2, qd = (lane & 3) * 2;

    float acc[4][4][4];
    #pragma unroll
    for (int a = 0; a < 4; a++)
        #pragma unroll
        for (int b = 0; b < 4; b++)
            #pragma unroll
            for (int c = 0; c < 4; c++) acc[a][b][c] = 0.f;

    #pragma unroll
    for (int ks = 0; ks < 8; ks++) {
        int kc = ks * 16 + qd;
        uint32_t af[4][4], bf[4][2];
        #pragma unroll
        for (int ms = 0; ms < 4; ms++) {
            const __nv_bfloat16* p = &As[(m0 + ms * 16 + gid) * GM_STRIDE + kc];
            af[ms][0] = *(const uint32_t*)p;
            af[ms][1] = *(const uint32_t*)(p + 8 * GM_STRIDE);
            af[ms][2] = *(const uint32_t*)(p + 8);
            af[ms][3] = *(const uint32_t*)(p + 8 * GM_STRIDE + 8);
        }
        #pragma unroll
        for (int ns = 0; ns < 4; ns++) {
            const __nv_bfloat16* p = &Bs[(n0 + ns * 8 + gid) * GM_STRIDE + kc];
            bf[ns][0] = *(const uint32_t*)p;
            bf[ns][1] = *(const uint32_t*)(p + 8);
        }
        #pragma unroll
        for (int ms = 0; ms < 4; ms++)
            #pragma unroll
            for (int ns = 0; ns < 4; ns++)
                MMA16816(acc[ms][ns], af[ms], bf[ns]);
    }

    // ---- epilogue: bias (+leaky), bf16 stores ----
    #pragma unroll
    for (int ms = 0; ms < 4; ms++) {
        int r1 = row0 + m0 + ms * 16 + gid;
        int r2 = r1 + 8;
        #pragma unroll
        for (int ns = 0; ns < 4; ns++) {
            int col = n0 + ns * 8 + qd;
            float2 b2 = *(const float2*)&bias[col];
            float v0 = acc[ms][ns][0] + b2.x, v1 = acc[ms][ns][1] + b2.y;
            float v2 = acc[ms][ns][2] + b2.x, v3 = acc[ms][ns][3] + b2.y;
            if (act) { v0 = leaky_f(v0); v1 = leaky_f(v1); v2 = leaky_f(v2); v3 = leaky_f(v3); }
            if (r1 < NN) *(__nv_bfloat162*)&g_hvalb[(size_t)r1 * HH + col] = __floats2bfloat162_rn(v0, v1);
            if (r2 < NN) *(__nv_bfloat162*)&g_hvalb[(size_t)r2 * HH + col] = __floats2bfloat162_rn(v2, v3);
        }
    }
}

// ---------------- layer-0 scores (h from k_input) -> buffer 0 ----------------
__global__ void k_scores1(const float* __restrict__ asrc, const float* __restrict__ adst) {
    int w = (blockIdx.x * blockDim.x + threadIdx.x) >> 5;
    int lane = threadIdx.x & 31;
    if (w >= NN) return;
    float a = 0.f, b = 0.f;
    #pragma unroll
    for (int q = 0; q < 4; q++) {
        int f = lane + q * 32;
        float hv = __bfloat162float(g_hb[(size_t)w * HH + f]);
        a += hv * asrc[f];
        b += hv * adst[f];
    }
    #pragma unroll
    for (int o = 16; o; o >>= 1) {
        a += __shfl_xor_sync(0xffffffffu, a, o);
        b += __shfl_xor_sync(0xffffffffu, b, o);
    }
    if (lane == 0) { g_ssrc[0][w] = a; g_sdst[0][w] = b; }
}

// ---------------- attention + BN + residual + leaky + NEXT-layer scores ----------------
// 2 edges per warp iteration: lanes 0-15 even edges, 16-31 odd edges; 8 features/lane.
__global__ void __launch_bounds__(256) k_attn(const float* __restrict__ bn_g,
                                              const float* __restrict__ bn_b,
                                              const float* __restrict__ bn_m,
                                              const float* __restrict__ bn_v,
                                              int residual, int multi, int rb,
                                              const float* __restrict__ nxt_asrc,
                                              const float* __restrict__ nxt_adst,
                                              int nxt_heads) {
    int w = (blockIdx.x * blockDim.x + threadIdx.x) >> 5;
    int lane = threadIdx.x & 31;
    if (w >= NN) return;
    int s0 = g_rowptr[w], e0 = g_rowptr[w + 1];
    int half = lane >> 4, l16 = lane & 15;
    int f0 = l16 * 8;                       // 8 consecutive features per lane
    int hd = multi ? (l16 >> 2) : 0;        // head of this lane's features
    const float* srcb = g_ssrc[rb];
    const float* dstb = g_sdst[rb];
    float si = multi ? srcb[w * 4 + hd] : srcb[w];

    float a[8] = {0, 0, 0, 0, 0, 0, 0, 0};
    float s = 0.f;
    const uint4* hb = (const uint4*)g_hvalb;    // row = 16 uint4
    for (int j = s0 + half; j < e0; j += 2) {
        int c = __ldg(&g_cols[j]);
        float sd = multi ? __ldg(&dstb[c * 4 + hd]) : __ldg(&dstb[c]);
        float wgt = __expf(leaky_f(si + sd));
        uint4 hv = __ldg(&hb[(size_t)c * 16 + l16]);
        float2 p0 = __bfloat1622float2(*(const __nv_bfloat162*)&hv.x);
        float2 p1 = __bfloat1622float2(*(const __nv_bfloat162*)&hv.y);
        float2 p2 = __bfloat1622float2(*(const __nv_bfloat162*)&hv.z);
        float2 p3 = __bfloat1622float2(*(const __nv_bfloat162*)&hv.w);
        s += wgt;
        a[0] += wgt * p0.x; a[1] += wgt * p0.y;
        a[2] += wgt * p1.x; a[3] += wgt * p1.y;
        a[4] += wgt * p2.x; a[5] += wgt * p2.y;
        a[6] += wgt * p3.x; a[7] += wgt * p3.y;
    }
    // combine halves (lanes L and L+16 end with identical sums)
    #pragma unroll
    for (int i = 0; i < 8; i++) a[i] += __shfl_xor_sync(0xffffffffu, a[i], 16);
    s += __shfl_xor_sync(0xffffffffu, s, 16);

    float inv = 1.f / (s + 1e-16f);
    float o[8];
    float4 m0 = *(const float4*)&bn_m[f0], m1 = *(const float4*)&bn_m[f0 + 4];
    float4 v0 = *(const float4*)&bn_v[f0], v1 = *(const float4*)&bn_v[f0 + 4];
    float4 gg0 = *(const float4*)&bn_g[f0], gg1 = *(const float4*)&bn_g[f0 + 4];
    float4 bb0 = *(const float4*)&bn_b[f0], bb1 = *(const float4*)&bn_b[f0 + 4];
    float mm[8] = {m0.x, m0.y, m0.z, m0.w, m1.x, m1.y, m1.z, m1.w};
    float vv[8] = {v0.x, v0.y, v0.z, v0.w, v1.x, v1.y, v1.z, v1.w};
    float gv[8] = {gg0.x, gg0.y, gg0.z, gg0.w, gg1.x, gg1.y, gg1.z, gg1.w};
    float bv[8] = {bb0.x, bb0.y, bb0.z, bb0.w, bb1.x, bb1.y, bb1.z, bb1.w};
    float rr[8] = {0, 0, 0, 0, 0, 0, 0, 0};
    if (residual) {
        uint4 rv = *(const uint4*)&g_hb[(size_t)w * HH + f0];
        float2 q0 = __bfloat1622float2(*(const __nv_bfloat162*)&rv.x);
        float2 q1 = __bfloat1622float2(*(const __nv_bfloat162*)&rv.y);
        float2 q2 = __bfloat1622float2(*(const __nv_bfloat162*)&rv.z);
        float2 q3 = __bfloat1622float2(*(const __nv_bfloat162*)&rv.w);
        rr[0] = q0.x; rr[1] = q0.y; rr[2] = q1.x; rr[3] = q1.y;
        rr[4] = q2.x; rr[5] = q2.y; rr[6] = q3.x; rr[7] = q3.y;
    }
    #pragma unroll
    for (int i = 0; i < 8; i++) {
        float t = (a[i] * inv - mm[i]) * (gv[i] * rsqrtf(vv[i] + BN_EPS)) + bv[i] + rr[i];
        o[i] = leaky_f(t);
    }
    if (half == 0) {
        uint4 st;
        __nv_bfloat162 c0 = __floats2bfloat162_rn(o[0], o[1]);
        __nv_bfloat162 c1 = __floats2bfloat162_rn(o[2], o[3]);
        __nv_bfloat162 c2 = __floats2bfloat162_rn(o[4], o[5]);
        __nv_bfloat162 c3 = __floats2bfloat162_rn(o[6], o[7]);
        st.x = *(uint32_t*)&c0; st.y = *(uint32_t*)&c1;
        st.z = *(uint32_t*)&c2; st.w = *(uint32_t*)&c3;
        *(uint4*)&g_hb[(size_t)w * HH + f0] = st;
    }

    // ---- fused next-layer scores (reduce over lanes 0-15; upper half mirrors) ----
    if (nxt_heads == 1) {
        float pa = 0.f, pb = 0.f;
        #pragma unroll
        for (int i = 0; i < 8; i++) {
            pa += o[i] * nxt_asrc[f0 + i];
            pb += o[i] * nxt_adst[f0 + i];
        }
        #pragma unroll
        for (int off = 8; off; off >>= 1) {
            pa += __shfl_xor_sync(0xffffffffu, pa, off);
            pb += __shfl_xor_sync(0xffffffffu, pb, off);
        }
        if (lane == 0) { g_ssrc[rb ^ 1][w] = pa; g_sdst[rb ^ 1][w] = pb; }
    } else if (nxt_heads == 4) {
        #pragma unroll
        for (int hh = 0; hh < 4; hh++) {
            float pa = 0.f, pb = 0.f;
            #pragma unroll
            for (int i = 0; i < 8; i++) {
                pa += o[i] * nxt_asrc[hh * HH + f0 + i];
                pb += o[i] * nxt_adst[hh * HH + f0 + i];
            }
            #pragma unroll
            for (int off = 8; off; off >>= 1) {
                pa += __shfl_xor_sync(0xffffffffu, pa, off);
                pb += __shfl_xor_sync(0xffffffffu, pb, off);
            }
            if (lane == 0) { g_ssrc[rb ^ 1][w * 4 + hh] = pa; g_sdst[rb ^ 1][w * 4 + hh] = pb; }
        }
    }
}

// ---------------- output head: out = x[:,15:18] + (hval @ W_o2 + b_o2) ----------------
__global__ void k_out(const float* __restrict__ x, const float* __restrict__ Wo2,
                      const float* __restrict__ bo2, float* __restrict__ out) {
    int w = (blockIdx.x * blockDim.x + threadIdx.x) >> 5;
    int lane = threadIdx.x & 31;
    if (w >= NN) return;
    float a0 = 0.f, a1 = 0.f, a2 = 0.f;
    #pragma unroll
    for (int q = 0; q < 4; q++) {
        int f = lane + q * 32;
        float t = __bfloat162float(g_hvalb[(size_t)w * HH + f]);
        a0 += t * Wo2[f * 3 + 0];
        a1 += t * Wo2[f * 3 + 1];
        a2 += t * Wo2[f * 3 + 2];
    }
    #pragma unroll
    for (int o = 16; o; o >>= 1) {
        a0 += __shfl_xor_sync(0xffffffffu, a0, o);
        a1 += __shfl_xor_sync(0xffffffffu, a1, o);
        a2 += __shfl_xor_sync(0xffffffffu, a2, o);
    }
    if (lane < 3) {
        float a = (lane == 0) ? a0 : (lane == 1) ? a1 : a2;
        out[w * 3 + lane] = x[w * DIN + 15 + lane] + a + bo2[lane];
    }
}

// ---------------- launch ----------------
extern "C" void kernel_launch(void* const* d_in, const int* in_sizes, int n_in,
                              void* d_out, int out_size) {
    const float* x     = (const float*)d_in[0];
    const int*   ei    = (const int*)d_in[1];
    const float* Win   = (const float*)d_in[2];
    const float* bin   = (const float*)d_in[3];
    const float* Wagg  = (const float*)d_in[4];
    const float* bagg  = (const float*)d_in[5];
    const float* shWv  = (const float*)d_in[6];
    const float* shb   = (const float*)d_in[7];
    const float* shas  = (const float*)d_in[8];
    const float* shad  = (const float*)d_in[9];
    const float* mhWv  = (const float*)d_in[10];
    const float* mhb   = (const float*)d_in[11];
    const float* mhas  = (const float*)d_in[12];
    const float* mhad  = (const float*)d_in[13];
    const float* bng   = (const float*)d_in[14];
    const float* bnb   = (const float*)d_in[15];
    const float* bnm   = (const float*)d_in[16];
    const float* bnv   = (const float*)d_in[17];
    const float* Wo1   = (const float*)d_in[18];
    const float* bo1   = (const float*)d_in[19];
    const float* Wo2   = (const float*)d_in[20];
    const float* bo2   = (const float*)d_in[21];
    float* out = (float*)d_out;

    cudaFuncSetAttribute(k_gemm_mma, cudaFuncAttributeMaxDynamicSharedMemorySize, GM_SM_TOTAL);

    const int WPB = 8;
    dim3 nwarp_grid((NN + WPB - 1) / WPB);
    dim3 mma_grid((NN + 127) / 128);

    // CSR build + weight conversion
    k_zero<<<(NN + 255) / 256, 256>>>();
    k_count<<<(EE + 255) / 256, 256>>>(ei);
    k_scan<<<1, 1024>>>();
    k_scatter<<<(EE + 255) / 256, 256>>>(ei);
    k_wt<<<(4 * HH * HH + 255) / 256, 256>>>(shWv, mhWv, Wo1);

    // input transform + layer-0 scores (buffer 0)
    k_nmean<<<nwarp_grid, WPB * 32>>>(x);
    k_input<<<(NN + 31) / 32, 128>>>(x, Win, bin, Wagg, bagg);
    k_scores1<<<nwarp_grid, WPB * 32>>>(shas, shad);

    // layer 0: single-head, BN[0], residual; reads buf0, emits 4-head scores -> buf1
    k_gemm_mma<<<mma_grid, 256, GM_SM_TOTAL>>>(0, shb, 0);
    k_attn<<<nwarp_grid, WPB * 32>>>(bng, bnb, bnm, bnv, 1, 0, 0, mhas, mhad, 4);

    // layer 1: multi-head, BN[1], no residual; reads buf1, emits layer-2 scores -> buf0
    k_gemm_mma<<<mma_grid, 256, GM_SM_TOTAL>>>(1, mhb, 0);
    k_attn<<<nwarp_grid, WPB * 32>>>(bng + HH, bnb + HH, bnm + HH, bnv + HH, 0, 1, 1,
                                     shas + HH, shad + HH, 1);

    // layer 2: single-head (set 1), BN[2], residual; reads buf0, no next scores
    k_gemm_mma<<<mma_grid, 256, GM_SM_TOTAL>>>(2, shb + HH, 0);
    k_attn<<<nwarp_grid, WPB * 32>>>(bng + 2 * HH, bnb + 2 * HH, bnm + 2 * HH, bnv + 2 * HH,
                                     1, 0, 0, nullptr, nullptr, 0);

    // output head
    k_gemm_mma<<<mma_grid, 256, GM_SM_TOTAL>>>(3, bo1, 1);
    k_out<<<nwarp_grid, WPB * 32>>>(x, Wo2, bo2, out);
}